// round 8
// baseline (speedup 1.0000x reference)
#include <cuda_runtime.h>
#include <cstdint>
#include <cstddef>

#define BM 128
#define BN 128
#define BK 16
#define SKEW 20   // smem row stride in floats: (r*20 + c) % 32 conflict-free for fragment loads

// Scratch (allocation-free rule: __device__ globals)
static __device__ float g_qkv [(size_t)16384 * 3072];   // 201 MB
static __device__ float g_attn[(size_t)16384 * 1024];   //  67 MB

__device__ __forceinline__ unsigned f2tf(float f) {
    unsigned u;
    asm("cvt.rna.tf32.f32 %0, %1;" : "=r"(u) : "f"(f));
    return u;
}

__device__ __forceinline__ void mma_tf32(float c[4], const unsigned a[4], const unsigned b[2]) {
    asm volatile(
        "mma.sync.aligned.m16n8k8.row.col.f32.tf32.tf32.f32 "
        "{%0,%1,%2,%3}, {%4,%5,%6,%7}, {%8,%9}, {%0,%1,%2,%3};\n"
        : "+f"(c[0]), "+f"(c[1]), "+f"(c[2]), "+f"(c[3])
        : "r"(a[0]), "r"(a[1]), "r"(a[2]), "r"(a[3]), "r"(b[0]), "r"(b[1]));
}

// C[m,n] = sum_k A[m,k] * Bm[n,k]  (+ bias[n]) ; all row-major, K contiguous (NT GEMM)
template <bool HAS_BIAS>
__global__ void __launch_bounds__(256)
gemm_tf32_nt(const float* __restrict__ A, const float* __restrict__ Bm,
             const float* __restrict__ bias, float* __restrict__ C,
             int M, int Nd, int K)
{
    __shared__ unsigned As[2][BM * SKEW];
    __shared__ unsigned Bs[2][BN * SKEW];

    const int tid  = threadIdx.x;
    const int warp = tid >> 5;
    const int lane = tid & 31;
    const int g    = lane >> 2;   // group id 0..7
    const int c    = lane & 3;    // thread-in-group 0..3

    const int bm0 = blockIdx.y * BM;
    const int bn0 = blockIdx.x * BN;

    const int wm = (warp >> 2) * 64;   // warp tile: 64 (M) x 32 (N)
    const int wn = (warp & 3) * 32;

    // global-load mapping: thread loads rows r0 and r0+64, float4 at column q0
    const int r0 = tid >> 2;          // 0..63
    const int q0 = (tid & 3) * 4;     // 0,4,8,12

    const float* Ag0 = A  + (size_t)(bm0 + r0)      * K + q0;
    const float* Ag1 = A  + (size_t)(bm0 + r0 + 64) * K + q0;
    const float* Bg0 = Bm + (size_t)(bn0 + r0)      * K + q0;
    const float* Bg1 = Bm + (size_t)(bn0 + r0 + 64) * K + q0;

    float acc[4][4][4];
    #pragma unroll
    for (int i = 0; i < 4; i++)
        #pragma unroll
        for (int j = 0; j < 4; j++)
            #pragma unroll
            for (int r = 0; r < 4; r++) acc[i][j][r] = 0.f;

    const int sA0 =  r0       * SKEW + q0;
    const int sA1 = (r0 + 64) * SKEW + q0;

    // ---- prologue: load tile 0 into smem buf 0 ----
    {
        float4 a0 = *(const float4*)Ag0;
        float4 a1 = *(const float4*)Ag1;
        float4 b0 = *(const float4*)Bg0;
        float4 b1 = *(const float4*)Bg1;
        *(uint4*)&As[0][sA0] = make_uint4(f2tf(a0.x), f2tf(a0.y), f2tf(a0.z), f2tf(a0.w));
        *(uint4*)&As[0][sA1] = make_uint4(f2tf(a1.x), f2tf(a1.y), f2tf(a1.z), f2tf(a1.w));
        *(uint4*)&Bs[0][sA0] = make_uint4(f2tf(b0.x), f2tf(b0.y), f2tf(b0.z), f2tf(b0.w));
        *(uint4*)&Bs[0][sA1] = make_uint4(f2tf(b1.x), f2tf(b1.y), f2tf(b1.z), f2tf(b1.w));
    }
    __syncthreads();

    const int nIter = K / BK;   // 64
    float4 ra0, ra1, rb0, rb1;

    for (int it = 0; it < nIter; ++it) {
        const int cur = it & 1;
        const int nxt = cur ^ 1;

        if (it + 1 < nIter) {
            const int k1 = (it + 1) * BK;
            ra0 = *(const float4*)(Ag0 + k1);
            ra1 = *(const float4*)(Ag1 + k1);
            rb0 = *(const float4*)(Bg0 + k1);
            rb1 = *(const float4*)(Bg1 + k1);
        }

        const unsigned* __restrict__ Acur = As[cur];
        const unsigned* __restrict__ Bcur = Bs[cur];

        #pragma unroll
        for (int kk = 0; kk < BK; kk += 8) {
            unsigned af[4][4];
            #pragma unroll
            for (int i = 0; i < 4; i++) {
                const int base = (wm + i * 16 + g) * SKEW + kk + c;
                af[i][0] = Acur[base];
                af[i][1] = Acur[base + 8 * SKEW];
                af[i][2] = Acur[base + 4];
                af[i][3] = Acur[base + 8 * SKEW + 4];
            }
            unsigned bf[4][2];
            #pragma unroll
            for (int j = 0; j < 4; j++) {
                const int base = (wn + j * 8 + g) * SKEW + kk + c;
                bf[j][0] = Bcur[base];
                bf[j][1] = Bcur[base + 4];
            }
            #pragma unroll
            for (int i = 0; i < 4; i++)
                #pragma unroll
                for (int j = 0; j < 4; j++)
                    mma_tf32(acc[i][j], af[i], bf[j]);
        }

        if (it + 1 < nIter) {
            *(uint4*)&As[nxt][sA0] = make_uint4(f2tf(ra0.x), f2tf(ra0.y), f2tf(ra0.z), f2tf(ra0.w));
            *(uint4*)&As[nxt][sA1] = make_uint4(f2tf(ra1.x), f2tf(ra1.y), f2tf(ra1.z), f2tf(ra1.w));
            *(uint4*)&Bs[nxt][sA0] = make_uint4(f2tf(rb0.x), f2tf(rb0.y), f2tf(rb0.z), f2tf(rb0.w));
            *(uint4*)&Bs[nxt][sA1] = make_uint4(f2tf(rb1.x), f2tf(rb1.y), f2tf(rb1.z), f2tf(rb1.w));
            __syncthreads();
        }
    }

    // ---- epilogue ----
    #pragma unroll
    for (int i = 0; i < 4; i++) {
        const int row = bm0 + wm + i * 16 + g;
        #pragma unroll
        for (int j = 0; j < 4; j++) {
            const int col = bn0 + wn + j * 8 + c * 2;
            float2 add = make_float2(0.f, 0.f);
            if (HAS_BIAS) add = *(const float2*)(bias + col);
            float2 v0 = make_float2(acc[i][j][0] + add.x, acc[i][j][1] + add.y);
            float2 v1 = make_float2(acc[i][j][2] + add.x, acc[i][j][3] + add.y);
            *(float2*)(C + (size_t)row       * Nd + col) = v0;
            *(float2*)(C + (size_t)(row + 8) * Nd + col) = v1;
        }
    }
}

// Per-position cross-head attention: one block (128 thr) per (b,n) position.
// qkv layout per position: [q(16x64) | k(16x64) | v(16x64)] = 3072 contiguous floats.
__global__ void __launch_bounds__(128)
attn_kernel(const float* __restrict__ qkv, float* __restrict__ attn)
{
    __shared__ float s[3072];
    __shared__ float sS[16 * 17];
    __shared__ float sW[16 * 17];

    const int tid = threadIdx.x;
    const size_t m = blockIdx.x;

    const float4* src = (const float4*)(qkv + m * 3072);
    float4* dst = (float4*)s;
    #pragma unroll
    for (int i = 0; i < 6; i++) dst[tid + i * 128] = src[tid + i * 128];
    __syncthreads();

    const float* q = s;
    const float* k = s + 1024;
    const float* v = s + 2048;

    // scores[h][g] = (q[h]·k[g]) / 32 ; 256 entries, 2 per thread
    #pragma unroll
    for (int e = 0; e < 2; e++) {
        const int idx = tid + e * 128;
        const int h  = idx >> 4;
        const int gg = idx & 15;
        float sum = 0.f;
        #pragma unroll
        for (int d = 0; d < 64; d++) {
            const int dd = (d + gg) & 63;   // rotation kills stride-64 bank conflicts
            sum += q[h * 64 + dd] * k[gg * 64 + dd];
        }
        sS[h * 17 + gg] = sum * 0.03125f;   // 1/sqrt(1024)
    }
    __syncthreads();

    // softmax over g (16 wide), one row per thread
    if (tid < 16) {
        float mx = -1e30f;
        #pragma unroll
        for (int j = 0; j < 16; j++) mx = fmaxf(mx, sS[tid * 17 + j]);
        float w[16], sum = 0.f;
        #pragma unroll
        for (int j = 0; j < 16; j++) { w[j] = __expf(sS[tid * 17 + j] - mx); sum += w[j]; }
        const float inv = 1.f / sum;
        #pragma unroll
        for (int j = 0; j < 16; j++) sW[tid * 17 + j] = w[j] * inv;
    }
    __syncthreads();

    // attn[h][d] = sum_g w[h][g] * v[g][d] ; 8 outputs per thread
    const int h  = tid >> 3;
    const int d0 = (tid & 7) * 8;
    float out[8];
    #pragma unroll
    for (int j = 0; j < 8; j++) out[j] = 0.f;
    #pragma unroll
    for (int gg = 0; gg < 16; gg++) {
        const float w = sW[h * 17 + gg];
        #pragma unroll
        for (int j = 0; j < 8; j++) out[j] += w * v[gg * 64 + d0 + j];
    }
    float4* o4 = (float4*)(attn + m * 1024 + h * 64 + d0);
    o4[0] = make_float4(out[0], out[1], out[2], out[3]);
    o4[1] = make_float4(out[4], out[5], out[6], out[7]);
}

extern "C" void kernel_launch(void* const* d_in, const int* in_sizes, int n_in,
                              void* d_out, int out_size)
{
    const float* x    = (const float*)d_in[0];   // (4,4096,1024)
    const float* Wqkv = (const float*)d_in[1];   // (3072,1024)
    const float* Wo   = (const float*)d_in[2];   // (1024,1024)
    const float* bo   = (const float*)d_in[3];   // (1024)
    float* out = (float*)d_out;

    float *qkv = nullptr, *attn = nullptr;
    cudaGetSymbolAddress((void**)&qkv,  g_qkv);
    cudaGetSymbolAddress((void**)&attn, g_attn);

    const int M = 16384, K = 1024;

    gemm_tf32_nt<false><<<dim3(3072 / BN, M / BM), 256>>>(x,    Wqkv, nullptr, qkv, M, 3072, K);
    attn_kernel<<<M, 128>>>(qkv, attn);
    gemm_tf32_nt<true ><<<dim3(1024 / BN, M / BM), 256>>>(attn, Wo,   bo,      out, M, 1024, K);
}

// round 9
// speedup vs baseline: 1.0009x; 1.0009x over previous
#include <cuda_runtime.h>
#include <cstdint>
#include <cstddef>

#define BM 128
#define BN 128
#define BK 16
#define SKEW 20   // smem row stride in floats: (r*20 + c) % 32 conflict-free for fragment loads

// Scratch (allocation-free rule: __device__ globals)
static __device__ float g_qkv [(size_t)16384 * 3072];   // 201 MB
static __device__ float g_attn[(size_t)16384 * 1024];   //  67 MB

__device__ __forceinline__ unsigned f2tf(float f) {
    unsigned u;
    asm("cvt.rna.tf32.f32 %0, %1;" : "=r"(u) : "f"(f));
    return u;
}

__device__ __forceinline__ void mma_tf32(float c[4], const unsigned a[4], const unsigned b[2]) {
    asm volatile(
        "mma.sync.aligned.m16n8k8.row.col.f32.tf32.tf32.f32 "
        "{%0,%1,%2,%3}, {%4,%5,%6,%7}, {%8,%9}, {%0,%1,%2,%3};\n"
        : "+f"(c[0]), "+f"(c[1]), "+f"(c[2]), "+f"(c[3])
        : "r"(a[0]), "r"(a[1]), "r"(a[2]), "r"(a[3]), "r"(b[0]), "r"(b[1]));
}

// C[m,n] = sum_k A[m,k] * Bm[n,k]  (+ bias[n]) ; all row-major, K contiguous (NT GEMM)
template <bool HAS_BIAS>
__global__ void __launch_bounds__(256)
gemm_tf32_nt(const float* __restrict__ A, const float* __restrict__ Bm,
             const float* __restrict__ bias, float* __restrict__ C,
             int M, int Nd, int K)
{
    __shared__ unsigned As[2][BM * SKEW];
    __shared__ unsigned Bs[2][BN * SKEW];

    const int tid  = threadIdx.x;
    const int warp = tid >> 5;
    const int lane = tid & 31;
    const int g    = lane >> 2;   // group id 0..7
    const int c    = lane & 3;    // thread-in-group 0..3

    const int bm0 = blockIdx.y * BM;
    const int bn0 = blockIdx.x * BN;

    const int wm = (warp >> 2) * 64;   // warp tile: 64 (M) x 32 (N)
    const int wn = (warp & 3) * 32;

    // global-load mapping: thread loads rows r0 and r0+64, float4 at column q0
    const int r0 = tid >> 2;          // 0..63
    const int q0 = (tid & 3) * 4;     // 0,4,8,12

    const float* Ag0 = A  + (size_t)(bm0 + r0)      * K + q0;
    const float* Ag1 = A  + (size_t)(bm0 + r0 + 64) * K + q0;
    const float* Bg0 = Bm + (size_t)(bn0 + r0)      * K + q0;
    const float* Bg1 = Bm + (size_t)(bn0 + r0 + 64) * K + q0;

    float acc[4][4][4];
    #pragma unroll
    for (int i = 0; i < 4; i++)
        #pragma unroll
        for (int j = 0; j < 4; j++)
            #pragma unroll
            for (int r = 0; r < 4; r++) acc[i][j][r] = 0.f;

    const int sA0 =  r0       * SKEW + q0;
    const int sA1 = (r0 + 64) * SKEW + q0;

    // ---- prologue: load tile 0 into smem buf 0 ----
    {
        float4 a0 = *(const float4*)Ag0;
        float4 a1 = *(const float4*)Ag1;
        float4 b0 = *(const float4*)Bg0;
        float4 b1 = *(const float4*)Bg1;
        *(uint4*)&As[0][sA0] = make_uint4(f2tf(a0.x), f2tf(a0.y), f2tf(a0.z), f2tf(a0.w));
        *(uint4*)&As[0][sA1] = make_uint4(f2tf(a1.x), f2tf(a1.y), f2tf(a1.z), f2tf(a1.w));
        *(uint4*)&Bs[0][sA0] = make_uint4(f2tf(b0.x), f2tf(b0.y), f2tf(b0.z), f2tf(b0.w));
        *(uint4*)&Bs[0][sA1] = make_uint4(f2tf(b1.x), f2tf(b1.y), f2tf(b1.z), f2tf(b1.w));
    }
    __syncthreads();

    const int nIter = K / BK;   // 64
    float4 ra0, ra1, rb0, rb1;

    for (int it = 0; it < nIter; ++it) {
        const int cur = it & 1;
        const int nxt = cur ^ 1;

        if (it + 1 < nIter) {
            const int k1 = (it + 1) * BK;
            ra0 = *(const float4*)(Ag0 + k1);
            ra1 = *(const float4*)(Ag1 + k1);
            rb0 = *(const float4*)(Bg0 + k1);
            rb1 = *(const float4*)(Bg1 + k1);
        }

        const unsigned* __restrict__ Acur = As[cur];
        const unsigned* __restrict__ Bcur = Bs[cur];

        #pragma unroll
        for (int kk = 0; kk < BK; kk += 8) {
            unsigned af[4][4];
            #pragma unroll
            for (int i = 0; i < 4; i++) {
                const int base = (wm + i * 16 + g) * SKEW + kk + c;
                af[i][0] = Acur[base];
                af[i][1] = Acur[base + 8 * SKEW];
                af[i][2] = Acur[base + 4];
                af[i][3] = Acur[base + 8 * SKEW + 4];
            }
            unsigned bf[4][2];
            #pragma unroll
            for (int j = 0; j < 4; j++) {
                const int base = (wn + j * 8 + g) * SKEW + kk + c;
                bf[j][0] = Bcur[base];
                bf[j][1] = Bcur[base + 4];
            }
            #pragma unroll
            for (int i = 0; i < 4; i++)
                #pragma unroll
                for (int j = 0; j < 4; j++)
                    mma_tf32(acc[i][j], af[i], bf[j]);
        }

        if (it + 1 < nIter) {
            *(uint4*)&As[nxt][sA0] = make_uint4(f2tf(ra0.x), f2tf(ra0.y), f2tf(ra0.z), f2tf(ra0.w));
            *(uint4*)&As[nxt][sA1] = make_uint4(f2tf(ra1.x), f2tf(ra1.y), f2tf(ra1.z), f2tf(ra1.w));
            *(uint4*)&Bs[nxt][sA0] = make_uint4(f2tf(rb0.x), f2tf(rb0.y), f2tf(rb0.z), f2tf(rb0.w));
            *(uint4*)&Bs[nxt][sA1] = make_uint4(f2tf(rb1.x), f2tf(rb1.y), f2tf(rb1.z), f2tf(rb1.w));
            __syncthreads();
        }
    }

    // ---- epilogue ----
    #pragma unroll
    for (int i = 0; i < 4; i++) {
        const int row = bm0 + wm + i * 16 + g;
        #pragma unroll
        for (int j = 0; j < 4; j++) {
            const int col = bn0 + wn + j * 8 + c * 2;
            float2 add = make_float2(0.f, 0.f);
            if (HAS_BIAS) add = *(const float2*)(bias + col);
            float2 v0 = make_float2(acc[i][j][0] + add.x, acc[i][j][1] + add.y);
            float2 v1 = make_float2(acc[i][j][2] + add.x, acc[i][j][3] + add.y);
            *(float2*)(C + (size_t)row       * Nd + col) = v0;
            *(float2*)(C + (size_t)(row + 8) * Nd + col) = v1;
        }
    }
}

// Per-position cross-head attention: one block (128 thr) per (b,n) position.
// qkv layout per position: [q(16x64) | k(16x64) | v(16x64)] = 3072 contiguous floats.
__global__ void __launch_bounds__(128)
attn_kernel(const float* __restrict__ qkv, float* __restrict__ attn)
{
    __shared__ float s[3072];
    __shared__ float sS[16 * 17];
    __shared__ float sW[16 * 17];

    const int tid = threadIdx.x;
    const size_t m = blockIdx.x;

    const float4* src = (const float4*)(qkv + m * 3072);
    float4* dst = (float4*)s;
    #pragma unroll
    for (int i = 0; i < 6; i++) dst[tid + i * 128] = src[tid + i * 128];
    __syncthreads();

    const float* q = s;
    const float* k = s + 1024;
    const float* v = s + 2048;

    // scores[h][g] = (q[h]·k[g]) / 32 ; 256 entries, 2 per thread
    #pragma unroll
    for (int e = 0; e < 2; e++) {
        const int idx = tid + e * 128;
        const int h  = idx >> 4;
        const int gg = idx & 15;
        float sum = 0.f;
        #pragma unroll
        for (int d = 0; d < 64; d++) {
            const int dd = (d + gg) & 63;   // rotation kills stride-64 bank conflicts
            sum += q[h * 64 + dd] * k[gg * 64 + dd];
        }
        sS[h * 17 + gg] = sum * 0.03125f;   // 1/sqrt(1024)
    }
    __syncthreads();

    // softmax over g (16 wide), one row per thread
    if (tid < 16) {
        float mx = -1e30f;
        #pragma unroll
        for (int j = 0; j < 16; j++) mx = fmaxf(mx, sS[tid * 17 + j]);
        float w[16], sum = 0.f;
        #pragma unroll
        for (int j = 0; j < 16; j++) { w[j] = __expf(sS[tid * 17 + j] - mx); sum += w[j]; }
        const float inv = 1.f / sum;
        #pragma unroll
        for (int j = 0; j < 16; j++) sW[tid * 17 + j] = w[j] * inv;
    }
    __syncthreads();

    // attn[h][d] = sum_g w[h][g] * v[g][d] ; 8 outputs per thread
    const int h  = tid >> 3;
    const int d0 = (tid & 7) * 8;
    float out[8];
    #pragma unroll
    for (int j = 0; j < 8; j++) out[j] = 0.f;
    #pragma unroll
    for (int gg = 0; gg < 16; gg++) {
        const float w = sW[h * 17 + gg];
        #pragma unroll
        for (int j = 0; j < 8; j++) out[j] += w * v[gg * 64 + d0 + j];
    }
    float4* o4 = (float4*)(attn + m * 1024 + h * 64 + d0);
    o4[0] = make_float4(out[0], out[1], out[2], out[3]);
    o4[1] = make_float4(out[4], out[5], out[6], out[7]);
}

extern "C" void kernel_launch(void* const* d_in, const int* in_sizes, int n_in,
                              void* d_out, int out_size)
{
    const float* x    = (const float*)d_in[0];   // (4,4096,1024)
    const float* Wqkv = (const float*)d_in[1];   // (3072,1024)
    const float* Wo   = (const float*)d_in[2];   // (1024,1024)
    const float* bo   = (const float*)d_in[3];   // (1024)
    float* out = (float*)d_out;

    float *qkv = nullptr, *attn = nullptr;
    cudaGetSymbolAddress((void**)&qkv,  g_qkv);
    cudaGetSymbolAddress((void**)&attn, g_attn);

    const int M = 16384, K = 1024;

    gemm_tf32_nt<false><<<dim3(3072 / BN, M / BM), 256>>>(x,    Wqkv, nullptr, qkv, M, 3072, K);
    attn_kernel<<<M, 128>>>(qkv, attn);
    gemm_tf32_nt<true ><<<dim3(1024 / BN, M / BM), 256>>>(attn, Wo,   bo,      out, M, 1024, K);
}

// round 10
// speedup vs baseline: 1.0013x; 1.0004x over previous
#include <cuda_runtime.h>
#include <cstdint>
#include <cstddef>

#define BM 128
#define BN 128
#define BK 16
#define SKEW 20   // smem row stride in floats: (r*20 + c) % 32 conflict-free for fragment loads

// Scratch (allocation-free rule: __device__ globals)
static __device__ float g_qkv [(size_t)16384 * 3072];   // 201 MB
static __device__ float g_attn[(size_t)16384 * 1024];   //  67 MB

__device__ __forceinline__ unsigned f2tf(float f) {
    unsigned u;
    asm("cvt.rna.tf32.f32 %0, %1;" : "=r"(u) : "f"(f));
    return u;
}

__device__ __forceinline__ void mma_tf32(float c[4], const unsigned a[4], const unsigned b[2]) {
    asm volatile(
        "mma.sync.aligned.m16n8k8.row.col.f32.tf32.tf32.f32 "
        "{%0,%1,%2,%3}, {%4,%5,%6,%7}, {%8,%9}, {%0,%1,%2,%3};\n"
        : "+f"(c[0]), "+f"(c[1]), "+f"(c[2]), "+f"(c[3])
        : "r"(a[0]), "r"(a[1]), "r"(a[2]), "r"(a[3]), "r"(b[0]), "r"(b[1]));
}

// C[m,n] = sum_k A[m,k] * Bm[n,k]  (+ bias[n]) ; all row-major, K contiguous (NT GEMM)
template <bool HAS_BIAS>
__global__ void __launch_bounds__(256)
gemm_tf32_nt(const float* __restrict__ A, const float* __restrict__ Bm,
             const float* __restrict__ bias, float* __restrict__ C,
             int M, int Nd, int K)
{
    __shared__ unsigned As[2][BM * SKEW];
    __shared__ unsigned Bs[2][BN * SKEW];

    const int tid  = threadIdx.x;
    const int warp = tid >> 5;
    const int lane = tid & 31;
    const int g    = lane >> 2;   // group id 0..7
    const int c    = lane & 3;    // thread-in-group 0..3

    const int bm0 = blockIdx.y * BM;
    const int bn0 = blockIdx.x * BN;

    const int wm = (warp >> 2) * 64;   // warp tile: 64 (M) x 32 (N)
    const int wn = (warp & 3) * 32;

    // global-load mapping: thread loads rows r0 and r0+64, float4 at column q0
    const int r0 = tid >> 2;          // 0..63
    const int q0 = (tid & 3) * 4;     // 0,4,8,12

    const float* Ag0 = A  + (size_t)(bm0 + r0)      * K + q0;
    const float* Ag1 = A  + (size_t)(bm0 + r0 + 64) * K + q0;
    const float* Bg0 = Bm + (size_t)(bn0 + r0)      * K + q0;
    const float* Bg1 = Bm + (size_t)(bn0 + r0 + 64) * K + q0;

    float acc[4][4][4];
    #pragma unroll
    for (int i = 0; i < 4; i++)
        #pragma unroll
        for (int j = 0; j < 4; j++)
            #pragma unroll
            for (int r = 0; r < 4; r++) acc[i][j][r] = 0.f;

    const int sA0 =  r0       * SKEW + q0;
    const int sA1 = (r0 + 64) * SKEW + q0;

    // ---- prologue: load tile 0 into smem buf 0 ----
    {
        float4 a0 = *(const float4*)Ag0;
        float4 a1 = *(const float4*)Ag1;
        float4 b0 = *(const float4*)Bg0;
        float4 b1 = *(const float4*)Bg1;
        *(uint4*)&As[0][sA0] = make_uint4(f2tf(a0.x), f2tf(a0.y), f2tf(a0.z), f2tf(a0.w));
        *(uint4*)&As[0][sA1] = make_uint4(f2tf(a1.x), f2tf(a1.y), f2tf(a1.z), f2tf(a1.w));
        *(uint4*)&Bs[0][sA0] = make_uint4(f2tf(b0.x), f2tf(b0.y), f2tf(b0.z), f2tf(b0.w));
        *(uint4*)&Bs[0][sA1] = make_uint4(f2tf(b1.x), f2tf(b1.y), f2tf(b1.z), f2tf(b1.w));
    }
    __syncthreads();

    const int nIter = K / BK;   // 64
    float4 ra0, ra1, rb0, rb1;

    for (int it = 0; it < nIter; ++it) {
        const int cur = it & 1;
        const int nxt = cur ^ 1;

        if (it + 1 < nIter) {
            const int k1 = (it + 1) * BK;
            ra0 = *(const float4*)(Ag0 + k1);
            ra1 = *(const float4*)(Ag1 + k1);
            rb0 = *(const float4*)(Bg0 + k1);
            rb1 = *(const float4*)(Bg1 + k1);
        }

        const unsigned* __restrict__ Acur = As[cur];
        const unsigned* __restrict__ Bcur = Bs[cur];

        #pragma unroll
        for (int kk = 0; kk < BK; kk += 8) {
            unsigned af[4][4];
            #pragma unroll
            for (int i = 0; i < 4; i++) {
                const int base = (wm + i * 16 + g) * SKEW + kk + c;
                af[i][0] = Acur[base];
                af[i][1] = Acur[base + 8 * SKEW];
                af[i][2] = Acur[base + 4];
                af[i][3] = Acur[base + 8 * SKEW + 4];
            }
            unsigned bf[4][2];
            #pragma unroll
            for (int j = 0; j < 4; j++) {
                const int base = (wn + j * 8 + g) * SKEW + kk + c;
                bf[j][0] = Bcur[base];
                bf[j][1] = Bcur[base + 4];
            }
            #pragma unroll
            for (int i = 0; i < 4; i++)
                #pragma unroll
                for (int j = 0; j < 4; j++)
                    mma_tf32(acc[i][j], af[i], bf[j]);
        }

        if (it + 1 < nIter) {
            *(uint4*)&As[nxt][sA0] = make_uint4(f2tf(ra0.x), f2tf(ra0.y), f2tf(ra0.z), f2tf(ra0.w));
            *(uint4*)&As[nxt][sA1] = make_uint4(f2tf(ra1.x), f2tf(ra1.y), f2tf(ra1.z), f2tf(ra1.w));
            *(uint4*)&Bs[nxt][sA0] = make_uint4(f2tf(rb0.x), f2tf(rb0.y), f2tf(rb0.z), f2tf(rb0.w));
            *(uint4*)&Bs[nxt][sA1] = make_uint4(f2tf(rb1.x), f2tf(rb1.y), f2tf(rb1.z), f2tf(rb1.w));
            __syncthreads();
        }
    }

    // ---- epilogue ----
    #pragma unroll
    for (int i = 0; i < 4; i++) {
        const int row = bm0 + wm + i * 16 + g;
        #pragma unroll
        for (int j = 0; j < 4; j++) {
            const int col = bn0 + wn + j * 8 + c * 2;
            float2 add = make_float2(0.f, 0.f);
            if (HAS_BIAS) add = *(const float2*)(bias + col);
            float2 v0 = make_float2(acc[i][j][0] + add.x, acc[i][j][1] + add.y);
            float2 v1 = make_float2(acc[i][j][2] + add.x, acc[i][j][3] + add.y);
            *(float2*)(C + (size_t)row       * Nd + col) = v0;
            *(float2*)(C + (size_t)(row + 8) * Nd + col) = v1;
        }
    }
}

// Per-position cross-head attention: one block (128 thr) per (b,n) position.
// qkv layout per position: [q(16x64) | k(16x64) | v(16x64)] = 3072 contiguous floats.
__global__ void __launch_bounds__(128)
attn_kernel(const float* __restrict__ qkv, float* __restrict__ attn)
{
    __shared__ float s[3072];
    __shared__ float sS[16 * 17];
    __shared__ float sW[16 * 17];

    const int tid = threadIdx.x;
    const size_t m = blockIdx.x;

    const float4* src = (const float4*)(qkv + m * 3072);
    float4* dst = (float4*)s;
    #pragma unroll
    for (int i = 0; i < 6; i++) dst[tid + i * 128] = src[tid + i * 128];
    __syncthreads();

    const float* q = s;
    const float* k = s + 1024;
    const float* v = s + 2048;

    // scores[h][g] = (q[h]·k[g]) / 32 ; 256 entries, 2 per thread
    #pragma unroll
    for (int e = 0; e < 2; e++) {
        const int idx = tid + e * 128;
        const int h  = idx >> 4;
        const int gg = idx & 15;
        float sum = 0.f;
        #pragma unroll
        for (int d = 0; d < 64; d++) {
            const int dd = (d + gg) & 63;   // rotation kills stride-64 bank conflicts
            sum += q[h * 64 + dd] * k[gg * 64 + dd];
        }
        sS[h * 17 + gg] = sum * 0.03125f;   // 1/sqrt(1024)
    }
    __syncthreads();

    // softmax over g (16 wide), one row per thread
    if (tid < 16) {
        float mx = -1e30f;
        #pragma unroll
        for (int j = 0; j < 16; j++) mx = fmaxf(mx, sS[tid * 17 + j]);
        float w[16], sum = 0.f;
        #pragma unroll
        for (int j = 0; j < 16; j++) { w[j] = __expf(sS[tid * 17 + j] - mx); sum += w[j]; }
        const float inv = 1.f / sum;
        #pragma unroll
        for (int j = 0; j < 16; j++) sW[tid * 17 + j] = w[j] * inv;
    }
    __syncthreads();

    // attn[h][d] = sum_g w[h][g] * v[g][d] ; 8 outputs per thread
    const int h  = tid >> 3;
    const int d0 = (tid & 7) * 8;
    float out[8];
    #pragma unroll
    for (int j = 0; j < 8; j++) out[j] = 0.f;
    #pragma unroll
    for (int gg = 0; gg < 16; gg++) {
        const float w = sW[h * 17 + gg];
        #pragma unroll
        for (int j = 0; j < 8; j++) out[j] += w * v[gg * 64 + d0 + j];
    }
    float4* o4 = (float4*)(attn + m * 1024 + h * 64 + d0);
    o4[0] = make_float4(out[0], out[1], out[2], out[3]);
    o4[1] = make_float4(out[4], out[5], out[6], out[7]);
}

extern "C" void kernel_launch(void* const* d_in, const int* in_sizes, int n_in,
                              void* d_out, int out_size)
{
    const float* x    = (const float*)d_in[0];   // (4,4096,1024)
    const float* Wqkv = (const float*)d_in[1];   // (3072,1024)
    const float* Wo   = (const float*)d_in[2];   // (1024,1024)
    const float* bo   = (const float*)d_in[3];   // (1024)
    float* out = (float*)d_out;

    float *qkv = nullptr, *attn = nullptr;
    cudaGetSymbolAddress((void**)&qkv,  g_qkv);
    cudaGetSymbolAddress((void**)&attn, g_attn);

    const int M = 16384, K = 1024;

    gemm_tf32_nt<false><<<dim3(3072 / BN, M / BM), 256>>>(x,    Wqkv, nullptr, qkv, M, 3072, K);
    attn_kernel<<<M, 128>>>(qkv, attn);
    gemm_tf32_nt<true ><<<dim3(1024 / BN, M / BM), 256>>>(attn, Wo,   bo,      out, M, 1024, K);
}

// round 12
// speedup vs baseline: 1.1068x; 1.1053x over previous
#include <cuda_runtime.h>
#include <cstdint>
#include <cstddef>

#define BM 128
#define BN 128
#define BK 16
#define SKEW 20                    // smem row stride in words; conflict-free, 16B-aligned rows (80B)
#define STAGES 4
#define MAT_WORDS (BM * SKEW)              // 2560 words per matrix per stage
#define STAGE_WORDS (2 * MAT_WORDS)        // A + B
#define GEMM_SMEM (STAGES * STAGE_WORDS * 4)   // 81920 B -> 2 CTAs/SM

// ---------------- scratch (allocation-free rule: __device__ globals) ----------------
static __device__ float g_qkv [(size_t)16384 * 3072];   // 201 MB
static __device__ float g_attn[(size_t)16384 * 1024];   //  67 MB
static __device__ float g_xr  [(size_t)16384 * 1024];   //  64 MB  (tf32-rounded x)
static __device__ float g_wqkv[(size_t)3072  * 1024];   //  12 MB  (tf32-rounded Wqkv)
static __device__ float g_wo  [(size_t)1024  * 1024];   //   4 MB  (tf32-rounded Wo)

__device__ __forceinline__ unsigned f2tf(float f) {
    unsigned u;
    asm("cvt.rna.tf32.f32 %0, %1;" : "=r"(u) : "f"(f));
    return u;
}

__device__ __forceinline__ uint32_t smem_u32(const void* p) {
    uint32_t a;
    asm("{ .reg .u64 t; cvta.to.shared.u64 t, %1; cvt.u32.u64 %0, t; }"
        : "=r"(a) : "l"(p));
    return a;
}

__device__ __forceinline__ void mma_tf32(float c[4], const unsigned a[4], const unsigned b[2]) {
    asm volatile(
        "mma.sync.aligned.m16n8k8.row.col.f32.tf32.tf32.f32 "
        "{%0,%1,%2,%3}, {%4,%5,%6,%7}, {%8,%9}, {%0,%1,%2,%3};\n"
        : "+f"(c[0]), "+f"(c[1]), "+f"(c[2]), "+f"(c[3])
        : "r"(a[0]), "r"(a[1]), "r"(a[2]), "r"(a[3]), "r"(b[0]), "r"(b[1]));
}

// ---------------- tf32 pre-rounding pass ----------------
__global__ void __launch_bounds__(256)
round_tf32(const float* __restrict__ in, float* __restrict__ out, int n4)
{
    int i = blockIdx.x * blockDim.x + threadIdx.x;
    const int stride = gridDim.x * blockDim.x;
    const float4* src = (const float4*)in;
    float4* dst = (float4*)out;
    for (; i < n4; i += stride) {
        float4 v = src[i];
        v.x = __uint_as_float(f2tf(v.x));
        v.y = __uint_as_float(f2tf(v.y));
        v.z = __uint_as_float(f2tf(v.z));
        v.w = __uint_as_float(f2tf(v.w));
        dst[i] = v;
    }
}

// ---------------- tf32 NT-GEMM, 4 warps, warp tile 64x64, cp.async 4-stage ----------------
// C[m,n] = sum_k A[m,k]*B[n,k] (+bias[n]); A,B already tf32-rounded fp32, row-major, K contiguous.
template <bool HAS_BIAS>
__global__ void __launch_bounds__(128, 2)
gemm_tf32_cp(const float* __restrict__ A, const float* __restrict__ Bm,
             const float* __restrict__ bias, float* __restrict__ C,
             int M, int Nd, int K)
{
    extern __shared__ __align__(16) unsigned sm[];
    const uint32_t sbase = smem_u32(sm);

    const int tid  = threadIdx.x;
    const int warp = tid >> 5;
    const int lane = tid & 31;
    const int g    = lane >> 2;   // 0..7
    const int c    = lane & 3;    // 0..3

    const int bm0 = blockIdx.y * BM;
    const int bn0 = blockIdx.x * BN;

    const int wm = (warp >> 1) * 64;   // 2x2 warp raster, 64x64 warp tile
    const int wn = (warp &  1) * 64;

    // producer mapping: thread covers rows r0+32i (i=0..3), 16B quad q within 64B k-chunk row
    const int r0 = tid >> 2;      // 0..31
    const int q  = tid & 3;       // 0..3
    const float* Ag = A  + (size_t)(bm0 + r0) * K + q * 4;
    const float* Bg = Bm + (size_t)(bn0 + r0) * K + q * 4;

    float acc[4][8][4];
    #pragma unroll
    for (int i = 0; i < 4; i++)
        #pragma unroll
        for (int j = 0; j < 8; j++)
            #pragma unroll
            for (int r = 0; r < 4; r++) acc[i][j][r] = 0.f;

    const int nChunks = K / BK;   // 64

    // per-thread smem byte offsets (stage 0)
    uint32_t dA[4];
    #pragma unroll
    for (int i = 0; i < 4; i++)
        dA[i] = sbase + (uint32_t)(((r0 + 32 * i) * SKEW + q * 4) * 4);

    // ---- prologue: stages 0..STAGES-2 ----
    #pragma unroll
    for (int s = 0; s < STAGES - 1; s++) {
        const uint32_t so = (uint32_t)(s * STAGE_WORDS * 4);
        #pragma unroll
        for (int i = 0; i < 4; i++) {
            const float* ga = Ag + (size_t)(32 * i) * K + s * BK;
            const float* gb = Bg + (size_t)(32 * i) * K + s * BK;
            asm volatile("cp.async.cg.shared.global [%0], [%1], 16;" :: "r"(dA[i] + so), "l"(ga));
            asm volatile("cp.async.cg.shared.global [%0], [%1], 16;" :: "r"(dA[i] + so + MAT_WORDS * 4), "l"(gb));
        }
        asm volatile("cp.async.commit_group;");
    }

    for (int it = 0; it < nChunks; ++it) {
        asm volatile("cp.async.wait_group %0;" :: "n"(STAGES - 2));
        __syncthreads();

        // issue stage for chunk it+STAGES-1 (overwrites buffer consumed at iter it-1)
        const int kc = it + STAGES - 1;
        if (kc < nChunks) {
            const uint32_t so = (uint32_t)((kc % STAGES) * STAGE_WORDS * 4);
            #pragma unroll
            for (int i = 0; i < 4; i++) {
                const float* ga = Ag + (size_t)(32 * i) * K + kc * BK;
                const float* gb = Bg + (size_t)(32 * i) * K + kc * BK;
                asm volatile("cp.async.cg.shared.global [%0], [%1], 16;" :: "r"(dA[i] + so), "l"(ga));
                asm volatile("cp.async.cg.shared.global [%0], [%1], 16;" :: "r"(dA[i] + so + MAT_WORDS * 4), "l"(gb));
            }
        }
        asm volatile("cp.async.commit_group;");

        // compute on stage it%STAGES
        const unsigned* __restrict__ Acur = sm + (it % STAGES) * STAGE_WORDS;
        const unsigned* __restrict__ Bcur = Acur + MAT_WORDS;

        #pragma unroll
        for (int kk = 0; kk < BK; kk += 8) {
            unsigned af[4][4];
            #pragma unroll
            for (int i = 0; i < 4; i++) {
                const int base = (wm + i * 16 + g) * SKEW + kk + c;
                af[i][0] = Acur[base];
                af[i][1] = Acur[base + 8 * SKEW];
                af[i][2] = Acur[base + 4];
                af[i][3] = Acur[base + 8 * SKEW + 4];
            }
            unsigned bf[8][2];
            #pragma unroll
            for (int j = 0; j < 8; j++) {
                const int base = (wn + j * 8 + g) * SKEW + kk + c;
                bf[j][0] = Bcur[base];
                bf[j][1] = Bcur[base + 4];
            }
            #pragma unroll
            for (int i = 0; i < 4; i++)
                #pragma unroll
                for (int j = 0; j < 8; j++)
                    mma_tf32(acc[i][j], af[i], bf[j]);
        }
    }

    // ---- epilogue ----
    #pragma unroll
    for (int i = 0; i < 4; i++) {
        const int row = bm0 + wm + i * 16 + g;
        #pragma unroll
        for (int j = 0; j < 8; j++) {
            const int col = bn0 + wn + j * 8 + c * 2;
            float2 add = make_float2(0.f, 0.f);
            if (HAS_BIAS) add = *(const float2*)(bias + col);
            float2 v0 = make_float2(acc[i][j][0] + add.x, acc[i][j][1] + add.y);
            float2 v1 = make_float2(acc[i][j][2] + add.x, acc[i][j][3] + add.y);
            *(float2*)(C + (size_t)row       * Nd + col) = v0;
            *(float2*)(C + (size_t)(row + 8) * Nd + col) = v1;
        }
    }
}

// ---------------- per-position cross-head attention ----------------
// output stores are tf32-rounded so the O-projection GEMM can consume them directly.
__global__ void __launch_bounds__(128)
attn_kernel(const float* __restrict__ qkv, float* __restrict__ attn)
{
    __shared__ float s[3072];
    __shared__ float sS[16 * 17];
    __shared__ float sW[16 * 17];

    const int tid = threadIdx.x;
    const size_t m = blockIdx.x;

    const float4* src = (const float4*)(qkv + m * 3072);
    float4* dst = (float4*)s;
    #pragma unroll
    for (int i = 0; i < 6; i++) dst[tid + i * 128] = src[tid + i * 128];
    __syncthreads();

    const float* q = s;
    const float* k = s + 1024;
    const float* v = s + 2048;

    #pragma unroll
    for (int e = 0; e < 2; e++) {
        const int idx = tid + e * 128;
        const int h  = idx >> 4;
        const int gg = idx & 15;
        float sum = 0.f;
        #pragma unroll
        for (int d = 0; d < 64; d++) {
            const int dd = (d + gg) & 63;   // rotation kills stride-64 bank conflicts
            sum += q[h * 64 + dd] * k[gg * 64 + dd];
        }
        sS[h * 17 + gg] = sum * 0.03125f;   // 1/sqrt(1024)
    }
    __syncthreads();

    if (tid < 16) {
        float mx = -1e30f;
        #pragma unroll
        for (int j = 0; j < 16; j++) mx = fmaxf(mx, sS[tid * 17 + j]);
        float w[16], sum = 0.f;
        #pragma unroll
        for (int j = 0; j < 16; j++) { w[j] = __expf(sS[tid * 17 + j] - mx); sum += w[j]; }
        const float inv = 1.f / sum;
        #pragma unroll
        for (int j = 0; j < 16; j++) sW[tid * 17 + j] = w[j] * inv;
    }
    __syncthreads();

    const int h  = tid >> 3;
    const int d0 = (tid & 7) * 8;
    float out[8];
    #pragma unroll
    for (int j = 0; j < 8; j++) out[j] = 0.f;
    #pragma unroll
    for (int gg = 0; gg < 16; gg++) {
        const float w = sW[h * 17 + gg];
        #pragma unroll
        for (int j = 0; j < 8; j++) out[j] += w * v[gg * 64 + d0 + j];
    }
    float4* o4 = (float4*)(attn + m * 1024 + h * 64 + d0);
    o4[0] = make_float4(__uint_as_float(f2tf(out[0])), __uint_as_float(f2tf(out[1])),
                        __uint_as_float(f2tf(out[2])), __uint_as_float(f2tf(out[3])));
    o4[1] = make_float4(__uint_as_float(f2tf(out[4])), __uint_as_float(f2tf(out[5])),
                        __uint_as_float(f2tf(out[6])), __uint_as_float(f2tf(out[7])));
}

// ---------------- launch ----------------
extern "C" void kernel_launch(void* const* d_in, const int* in_sizes, int n_in,
                              void* d_out, int out_size)
{
    const float* x    = (const float*)d_in[0];   // (4,4096,1024)
    const float* Wqkv = (const float*)d_in[1];   // (3072,1024)
    const float* Wo   = (const float*)d_in[2];   // (1024,1024)
    const float* bo   = (const float*)d_in[3];   // (1024)
    float* out = (float*)d_out;

    float *qkv = nullptr, *attn = nullptr, *xr = nullptr, *wqkvr = nullptr, *wor = nullptr;
    cudaGetSymbolAddress((void**)&qkv,   g_qkv);
    cudaGetSymbolAddress((void**)&attn,  g_attn);
    cudaGetSymbolAddress((void**)&xr,    g_xr);
    cudaGetSymbolAddress((void**)&wqkvr, g_wqkv);
    cudaGetSymbolAddress((void**)&wor,   g_wo);

    cudaFuncSetAttribute(gemm_tf32_cp<false>, cudaFuncAttributeMaxDynamicSharedMemorySize, GEMM_SMEM);
    cudaFuncSetAttribute(gemm_tf32_cp<true >, cudaFuncAttributeMaxDynamicSharedMemorySize, GEMM_SMEM);

    const int M = 16384, K = 1024;

    // tf32 pre-rounding (cheap, HBM-streaming)
    round_tf32<<<4096, 256>>>(x,    xr,    (16384 * 1024) / 4);
    round_tf32<<<1536, 256>>>(Wqkv, wqkvr, (3072  * 1024) / 4);
    round_tf32<<<512,  256>>>(Wo,   wor,   (1024  * 1024) / 4);

    gemm_tf32_cp<false><<<dim3(3072 / BN, M / BM), 128, GEMM_SMEM>>>(xr,   wqkvr, nullptr, qkv, M, 3072, K);
    attn_kernel<<<M, 128>>>(qkv, attn);
    gemm_tf32_cp<true ><<<dim3(1024 / BN, M / BM), 128, GEMM_SMEM>>>(attn, wor,   bo,      out, M, 1024, K);
}

// round 13
// speedup vs baseline: 1.2302x; 1.1116x over previous
#include <cuda_runtime.h>
#include <cstdint>
#include <cstddef>

#define BM 128
#define BN 128
#define BK 32
#define SKW 36                         // smem row stride in words (128B data + 16B skew)
#define STAGES 3
#define MAT_WORDS (BM * SKW)           // 4608 words per matrix per stage
#define STAGE_WORDS (2 * MAT_WORDS)    // A + B = 9216 words
#define GEMM_SMEM (STAGES * STAGE_WORDS * 4)   // 110592 B -> 2 CTAs/SM

// ---------------- scratch (allocation-free rule: __device__ globals) ----------------
static __device__ float g_qkv [(size_t)16384 * 3072];   // 201 MB
static __device__ float g_attn[(size_t)16384 * 1024];   //  67 MB
static __device__ float g_xr  [(size_t)16384 * 1024];   //  64 MB  (tf32-rounded x)
static __device__ float g_wqkv[(size_t)3072  * 1024];   //  12 MB  (tf32-rounded Wqkv)
static __device__ float g_wo  [(size_t)1024  * 1024];   //   4 MB  (tf32-rounded Wo)

__device__ __forceinline__ unsigned f2tf(float f) {
    unsigned u;
    asm("cvt.rna.tf32.f32 %0, %1;" : "=r"(u) : "f"(f));
    return u;
}

__device__ __forceinline__ uint32_t smem_u32(const void* p) {
    uint32_t a;
    asm("{ .reg .u64 t; cvta.to.shared.u64 t, %1; cvt.u32.u64 %0, t; }"
        : "=r"(a) : "l"(p));
    return a;
}

__device__ __forceinline__ void mma_tf32(float c[4], const unsigned a[4], const unsigned b[2]) {
    asm volatile(
        "mma.sync.aligned.m16n8k8.row.col.f32.tf32.tf32.f32 "
        "{%0,%1,%2,%3}, {%4,%5,%6,%7}, {%8,%9}, {%0,%1,%2,%3};\n"
        : "+f"(c[0]), "+f"(c[1]), "+f"(c[2]), "+f"(c[3])
        : "r"(a[0]), "r"(a[1]), "r"(a[2]), "r"(a[3]), "r"(b[0]), "r"(b[1]));
}

// ---------------- tf32 pre-rounding pass ----------------
__global__ void __launch_bounds__(256)
round_tf32(const float* __restrict__ in, float* __restrict__ out, int n4)
{
    int i = blockIdx.x * blockDim.x + threadIdx.x;
    const int stride = gridDim.x * blockDim.x;
    const float4* src = (const float4*)in;
    float4* dst = (float4*)out;
    for (; i < n4; i += stride) {
        float4 v = src[i];
        v.x = __uint_as_float(f2tf(v.x));
        v.y = __uint_as_float(f2tf(v.y));
        v.z = __uint_as_float(f2tf(v.z));
        v.w = __uint_as_float(f2tf(v.w));
        dst[i] = v;
    }
}

// ---------------- tf32 NT-GEMM, 4 warps 64x64, BK=32, 3-stage cp.async, frag dbuf ----------------
template <bool HAS_BIAS>
__global__ void __launch_bounds__(128, 2)
gemm_tf32_cp(const float* __restrict__ A, const float* __restrict__ Bm,
             const float* __restrict__ bias, float* __restrict__ C,
             int M, int Nd, int K)
{
    extern __shared__ __align__(16) unsigned sm[];
    const uint32_t sbase = smem_u32(sm);

    const int tid  = threadIdx.x;
    const int warp = tid >> 5;
    const int lane = tid & 31;
    const int g    = lane >> 2;   // 0..7
    const int c    = lane & 3;    // 0..3

    const int bm0 = blockIdx.y * BM;
    const int bn0 = blockIdx.x * BN;

    const int wm = (warp >> 1) * 64;   // 2x2 warp raster, 64x64 warp tile
    const int wn = (warp &  1) * 64;

    // producer mapping: q = 16B quad within 128B row, r0 = row base, rows r0+16i (i=0..7)
    const int q  = tid & 7;       // 0..7
    const int r0 = tid >> 3;      // 0..15
    const float* Ag = A  + (size_t)(bm0 + r0) * K + q * 4;
    const float* Bg = Bm + (size_t)(bn0 + r0) * K + q * 4;

    float acc[4][8][4];
    #pragma unroll
    for (int i = 0; i < 4; i++)
        #pragma unroll
        for (int j = 0; j < 8; j++)
            #pragma unroll
            for (int r = 0; r < 4; r++) acc[i][j][r] = 0.f;

    const int nChunks = K / BK;   // 32

    // per-thread smem byte dst (stage 0): 8 rows per matrix
    uint32_t dA[8];
    #pragma unroll
    for (int i = 0; i < 8; i++)
        dA[i] = sbase + (uint32_t)(((r0 + 16 * i) * SKW + q * 4) * 4);

    // ---- prologue: stages 0..STAGES-2 ----
    #pragma unroll
    for (int s = 0; s < STAGES - 1; s++) {
        const uint32_t so = (uint32_t)(s * STAGE_WORDS * 4);
        #pragma unroll
        for (int i = 0; i < 8; i++) {
            const float* ga = Ag + (size_t)(16 * i) * K + s * BK;
            const float* gb = Bg + (size_t)(16 * i) * K + s * BK;
            asm volatile("cp.async.cg.shared.global [%0], [%1], 16;" :: "r"(dA[i] + so), "l"(ga));
            asm volatile("cp.async.cg.shared.global [%0], [%1], 16;" :: "r"(dA[i] + so + MAT_WORDS * 4), "l"(gb));
        }
        asm volatile("cp.async.commit_group;");
    }

    for (int it = 0; it < nChunks; ++it) {
        asm volatile("cp.async.wait_group %0;" :: "n"(STAGES - 2));
        __syncthreads();

        // issue stage for chunk it+STAGES-1 (stage consumed at iter it-1; barrier above protects it)
        const int kc = it + STAGES - 1;
        if (kc < nChunks) {
            const uint32_t so = (uint32_t)((kc % STAGES) * STAGE_WORDS * 4);
            #pragma unroll
            for (int i = 0; i < 8; i++) {
                const float* ga = Ag + (size_t)(16 * i) * K + kc * BK;
                const float* gb = Bg + (size_t)(16 * i) * K + kc * BK;
                asm volatile("cp.async.cg.shared.global [%0], [%1], 16;" :: "r"(dA[i] + so), "l"(ga));
                asm volatile("cp.async.cg.shared.global [%0], [%1], 16;" :: "r"(dA[i] + so + MAT_WORDS * 4), "l"(gb));
            }
        }
        asm volatile("cp.async.commit_group;");

        // compute on stage it%STAGES : 4 k8-steps, fragment double-buffered
        const unsigned* __restrict__ Acur = sm + (it % STAGES) * STAGE_WORDS;
        const unsigned* __restrict__ Bcur = Acur + MAT_WORDS;

        unsigned af[2][4][4], bf[2][8][2];

        // load k8-step 0 into buf 0
        #pragma unroll
        for (int i = 0; i < 4; i++) {
            const int base = (wm + i * 16 + g) * SKW + c;
            af[0][i][0] = Acur[base];
            af[0][i][1] = Acur[base + 8 * SKW];
            af[0][i][2] = Acur[base + 4];
            af[0][i][3] = Acur[base + 8 * SKW + 4];
        }
        #pragma unroll
        for (int j = 0; j < 8; j++) {
            const int base = (wn + j * 8 + g) * SKW + c;
            bf[0][j][0] = Bcur[base];
            bf[0][j][1] = Bcur[base + 4];
        }

        #pragma unroll
        for (int ks = 0; ks < 4; ks++) {
            const int cur = ks & 1;
            if (ks < 3) {                 // prefetch next k8-step into other buffer
                const int kk = (ks + 1) * 8;
                #pragma unroll
                for (int i = 0; i < 4; i++) {
                    const int base = (wm + i * 16 + g) * SKW + kk + c;
                    af[cur ^ 1][i][0] = Acur[base];
                    af[cur ^ 1][i][1] = Acur[base + 8 * SKW];
                    af[cur ^ 1][i][2] = Acur[base + 4];
                    af[cur ^ 1][i][3] = Acur[base + 8 * SKW + 4];
                }
                #pragma unroll
                for (int j = 0; j < 8; j++) {
                    const int base = (wn + j * 8 + g) * SKW + kk + c;
                    bf[cur ^ 1][j][0] = Bcur[base];
                    bf[cur ^ 1][j][1] = Bcur[base + 4];
                }
            }
            #pragma unroll
            for (int i = 0; i < 4; i++)
                #pragma unroll
                for (int j = 0; j < 8; j++)
                    mma_tf32(acc[i][j], af[cur][i], bf[cur][j]);
        }
    }

    // ---- epilogue ----
    #pragma unroll
    for (int i = 0; i < 4; i++) {
        const int row = bm0 + wm + i * 16 + g;
        #pragma unroll
        for (int j = 0; j < 8; j++) {
            const int col = bn0 + wn + j * 8 + c * 2;
            float2 add = make_float2(0.f, 0.f);
            if (HAS_BIAS) add = *(const float2*)(bias + col);
            float2 v0 = make_float2(acc[i][j][0] + add.x, acc[i][j][1] + add.y);
            float2 v1 = make_float2(acc[i][j][2] + add.x, acc[i][j][3] + add.y);
            *(float2*)(C + (size_t)row       * Nd + col) = v0;
            *(float2*)(C + (size_t)(row + 8) * Nd + col) = v1;
        }
    }
}

// ---------------- per-position cross-head attention ----------------
__global__ void __launch_bounds__(128)
attn_kernel(const float* __restrict__ qkv, float* __restrict__ attn)
{
    __shared__ float s[3072];
    __shared__ float sS[16 * 17];
    __shared__ float sW[16 * 17];

    const int tid = threadIdx.x;
    const size_t m = blockIdx.x;

    const float4* src = (const float4*)(qkv + m * 3072);
    float4* dst = (float4*)s;
    #pragma unroll
    for (int i = 0; i < 6; i++) dst[tid + i * 128] = src[tid + i * 128];
    __syncthreads();

    const float* q = s;
    const float* k = s + 1024;
    const float* v = s + 2048;

    #pragma unroll
    for (int e = 0; e < 2; e++) {
        const int idx = tid + e * 128;
        const int h  = idx >> 4;
        const int gg = idx & 15;
        float sum = 0.f;
        #pragma unroll
        for (int d = 0; d < 64; d++) {
            const int dd = (d + gg) & 63;   // rotation kills stride-64 bank conflicts
            sum += q[h * 64 + dd] * k[gg * 64 + dd];
        }
        sS[h * 17 + gg] = sum * 0.03125f;   // 1/sqrt(1024)
    }
    __syncthreads();

    if (tid < 16) {
        float mx = -1e30f;
        #pragma unroll
        for (int j = 0; j < 16; j++) mx = fmaxf(mx, sS[tid * 17 + j]);
        float w[16], sum = 0.f;
        #pragma unroll
        for (int j = 0; j < 16; j++) { w[j] = __expf(sS[tid * 17 + j] - mx); sum += w[j]; }
        const float inv = 1.f / sum;
        #pragma unroll
        for (int j = 0; j < 16; j++) sW[tid * 17 + j] = w[j] * inv;
    }
    __syncthreads();

    const int h  = tid >> 3;
    const int d0 = (tid & 7) * 8;
    float out[8];
    #pragma unroll
    for (int j = 0; j < 8; j++) out[j] = 0.f;
    #pragma unroll
    for (int gg = 0; gg < 16; gg++) {
        const float w = sW[h * 17 + gg];
        #pragma unroll
        for (int j = 0; j < 8; j++) out[j] += w * v[gg * 64 + d0 + j];
    }
    float4* o4 = (float4*)(attn + m * 1024 + h * 64 + d0);
    o4[0] = make_float4(__uint_as_float(f2tf(out[0])), __uint_as_float(f2tf(out[1])),
                        __uint_as_float(f2tf(out[2])), __uint_as_float(f2tf(out[3])));
    o4[1] = make_float4(__uint_as_float(f2tf(out[4])), __uint_as_float(f2tf(out[5])),
                        __uint_as_float(f2tf(out[6])), __uint_as_float(f2tf(out[7])));
}

// ---------------- launch ----------------
extern "C" void kernel_launch(void* const* d_in, const int* in_sizes, int n_in,
                              void* d_out, int out_size)
{
    const float* x    = (const float*)d_in[0];   // (4,4096,1024)
    const float* Wqkv = (const float*)d_in[1];   // (3072,1024)
    const float* Wo   = (const float*)d_in[2];   // (1024,1024)
    const float* bo   = (const float*)d_in[3];   // (1024)
    float* out = (float*)d_out;

    float *qkv = nullptr, *attn = nullptr, *xr = nullptr, *wqkvr = nullptr, *wor = nullptr;
    cudaGetSymbolAddress((void**)&qkv,   g_qkv);
    cudaGetSymbolAddress((void**)&attn,  g_attn);
    cudaGetSymbolAddress((void**)&xr,    g_xr);
    cudaGetSymbolAddress((void**)&wqkvr, g_wqkv);
    cudaGetSymbolAddress((void**)&wor,   g_wo);

    cudaFuncSetAttribute(gemm_tf32_cp<false>, cudaFuncAttributeMaxDynamicSharedMemorySize, GEMM_SMEM);
    cudaFuncSetAttribute(gemm_tf32_cp<true >, cudaFuncAttributeMaxDynamicSharedMemorySize, GEMM_SMEM);

    const int M = 16384, K = 1024;

    // tf32 pre-rounding (cheap, HBM-streaming)
    round_tf32<<<4096, 256>>>(x,    xr,    (16384 * 1024) / 4);
    round_tf32<<<1536, 256>>>(Wqkv, wqkvr, (3072  * 1024) / 4);
    round_tf32<<<512,  256>>>(Wo,   wor,   (1024  * 1024) / 4);

    gemm_tf32_cp<false><<<dim3(3072 / BN, M / BM), 128, GEMM_SMEM>>>(xr,   wqkvr, nullptr, qkv, M, 3072, K);
    attn_kernel<<<M, 128>>>(qkv, attn);
    gemm_tf32_cp<true ><<<dim3(1024 / BN, M / BM), 128, GEMM_SMEM>>>(attn, wor,   bo,      out, M, 1024, K);
}